// round 9
// baseline (speedup 1.0000x reference)
#include <cuda_runtime.h>
#include <math.h>
#include <stdint.h>

#define BB     32
#define NN     8732
#define NCLS   20
#define DCOL   33
#define NMSMAX 100
#define TOPK   200
#define CONF_T 0.01f
#define IOU_T  0.45f
#define TILE   128
#define NTILES 69            // ceil(8732/128)
#define NBC    (BB * NCLS)   // 640
#define CAP    384
#define STAGE  64
#define WPB    4             // warps per nms block
#define NMSBLOCKS (NBC / WPB)       // 160
#define BLK_PER_BATCH (NCLS / WPB)  // 5
#define DYN_SMEM 56000       // max(4*512*16, 16000+40000)

// ---------------- scratch ----------------
__device__ float4             g_boxes   [(size_t)BB * NN];
__device__ int                g_candcnt [NBC];            // zero-init; reset each pass
__device__ unsigned long long g_cand    [NBC * CAP];
__device__ float              g_selscore[NBC * NMSMAX];
__device__ float4             g_selbox  [NBC * NMSMAX];
__device__ int                g_batch_done[BB];           // zero-init; reset each pass

// monotonic float <-> u32 order-preserving map
__device__ __forceinline__ unsigned fmap(float f) {
    unsigned u = __float_as_uint(f);
    return (u & 0x80000000u) ? ~u : (u | 0x80000000u);
}
__device__ __forceinline__ float funmap(unsigned u) {
    return __uint_as_float((u & 0x80000000u) ? (u & 0x7FFFFFFFu) : ~u);
}
#define FM_NEGINF 0x007FFFFFu   // fmap(-inf)

__device__ __forceinline__ float4 decode_box_row(const float* __restrict__ r)
{
    float cx_p = r[21], cy_p = r[22], w_p = r[23], h_p = r[24];
    float xa1  = r[25], ya1  = r[26], xa2 = r[27], ya2 = r[28];
    float vcx  = r[29], vcy  = r[30], vw  = r[31], vh  = r[32];
    float w_a = xa2 - xa1, h_a = ya2 - ya1;
    float cx_a = (xa2 + xa1) * 0.5f, cy_a = (ya2 + ya1) * 0.5f;
    float cx = cx_p * vcx * w_a + cx_a;
    float cy = cy_p * vcy * h_a + cy_a;
    float w  = expf(w_p * vw) * w_a;
    float h  = expf(h_p * vh) * h_a;
    float4 o;
    o.x = (cx - 0.5f * w) * 512.0f;
    o.y = (cy - 0.5f * h) * 512.0f;
    o.z = (cx + 0.5f * w) * 512.0f;
    o.w = (cy + 0.5f * h) * 512.0f;
    return o;
}

// ---------------- phase 1: decode + staged candidate filter ----------------
__global__ void __launch_bounds__(256) decode_kernel(const float* __restrict__ y)
{
    __shared__ __align__(16) float sh[TILE * DCOL];
    __shared__ unsigned long long s_skey[NCLS * STAGE];
    __shared__ int s_scnt[NCLS];
    __shared__ int s_sbase[NCLS];

    const int tid = threadIdx.x;
    int blk = blockIdx.x;
    int b   = blk / NTILES;
    int t   = blk % NTILES;
    int n0  = t * TILE;
    int count = min(TILE, NN - n0);

    // vectorized tile load: count*DCOL is divisible by 4 for both tile sizes,
    // and the base offset (b*8732 + t*128)*33 floats is 16B-aligned.
    {
        const float4* src4 = (const float4*)(y + ((size_t)b * NN + n0) * DCOL);
        float4* sh4 = (float4*)sh;
        int n4 = (count * DCOL) >> 2;
        for (int i = tid; i < n4; i += 256) sh4[i] = src4[i];
        for (int i = (n4 << 2) + tid; i < count * DCOL; i += 256) sh[i] = y[((size_t)b * NN + n0) * DCOL + i];
    }
    if (tid < NCLS) s_scnt[tid] = 0;
    __syncthreads();

    const unsigned LO = fmap(0.975f);
    if (count == TILE) {
        for (int k = tid; k < NCLS * TILE; k += 256) {
            int c  = k >> 7;
            int nn = k & (TILE - 1);
            float s = sh[nn * DCOL + 1 + c];
            if (s > CONF_T) {
                unsigned m = fmap(s);
                if (m >= LO) {
                    unsigned long long key = ((unsigned long long)m << 32) |
                                             (unsigned)(0xFFFFFFFFu - (unsigned)(n0 + nn));
                    int p = atomicAdd(&s_scnt[c], 1);
                    if (p < STAGE) s_skey[c * STAGE + p] = key;
                    else {
                        int bc = b * NCLS + c;
                        int q = atomicAdd(&g_candcnt[bc], 1);
                        if (q < CAP) g_cand[bc * CAP + q] = key;
                    }
                }
            }
        }
    } else {
        for (int k = tid; k < NCLS * count; k += 256) {
            int c  = k / count;
            int nn = k - c * count;
            float s = sh[nn * DCOL + 1 + c];
            if (s > CONF_T) {
                unsigned m = fmap(s);
                if (m >= LO) {
                    unsigned long long key = ((unsigned long long)m << 32) |
                                             (unsigned)(0xFFFFFFFFu - (unsigned)(n0 + nn));
                    int p = atomicAdd(&s_scnt[c], 1);
                    if (p < STAGE) s_skey[c * STAGE + p] = key;
                    else {
                        int bc = b * NCLS + c;
                        int q = atomicAdd(&g_candcnt[bc], 1);
                        if (q < CAP) g_cand[bc * CAP + q] = key;
                    }
                }
            }
        }
    }
    __syncthreads();

    if (tid < NCLS) {
        int n = min(s_scnt[tid], STAGE);
        s_sbase[tid] = (n > 0) ? atomicAdd(&g_candcnt[b * NCLS + tid], n) : 0;
    }
    __syncthreads();
    for (int k = tid; k < NCLS * STAGE; k += 256) {
        int c = k >> 6;
        int j = k & (STAGE - 1);
        if (j < min(s_scnt[c], STAGE)) {
            int q = s_sbase[c] + j;
            if (q < CAP) g_cand[(b * NCLS + c) * CAP + q] = s_skey[c * STAGE + j];
        }
    }

    if (tid < count)
        g_boxes[(size_t)b * NN + n0 + tid] = decode_box_row(sh + tid * DCOL);
}

// ---------------- phase 2: warp NMS with lane-local kept registers ----------
template<int SLOTS>
__device__ __forceinline__ void process_window(
    const unsigned long long* __restrict__ src, int cnt,
    const float4* __restrict__ bx, int bc, int lane,
    float4* __restrict__ sbox,                     // per-warp smem: 512 float4
    int& ns, int& nkp,
    float4& kb0, float4& kb1, float4& kb2, float4& kb3,
    float& ka0, float& ka1, float& ka2, float& ka3)
{
    constexpr int LOG2N = (SLOTS == 8) ? 8 : 9;

    unsigned long long key[SLOTS];
    #pragma unroll
    for (int s = 0; s < SLOTS; ++s) {
        int p = s * 32 + lane;
        key[s] = (p < cnt) ? src[p] : 0ull;
    }

    // ---- warp bitonic sort, descending (slot-major: p = s*32 + lane) ----
    #pragma unroll
    for (int ksl = 1; ksl <= LOG2N; ++ksl) {
        const int ks = 1 << ksl;
        #pragma unroll
        for (int j = ks >> 1; j >= 32; j >>= 1) {
            const int js = j >> 5;
            #pragma unroll
            for (int s = 0; s < SLOTS; ++s) {
                const int sp = s ^ js;
                if (sp > s) {
                    bool descSeg = (((s * 32) & ks) == 0);
                    unsigned long long a = key[s], b2 = key[sp];
                    bool sw = descSeg ? (a < b2) : (a > b2);
                    if (sw) { key[s] = b2; key[sp] = a; }
                }
            }
        }
        for (int j = (ks >> 1) < 32 ? (ks >> 1) : 16; j > 0; j >>= 1) {
            #pragma unroll
            for (int s = 0; s < SLOTS; ++s) {
                int p = s * 32 + lane;
                unsigned long long pv = __shfl_xor_sync(0xFFFFFFFFu, key[s], j);
                bool lower   = ((lane & j) == 0);
                bool descSeg = ((p & ks) == 0);
                bool takeMax = (lower == descSeg);
                unsigned long long mx = (key[s] > pv) ? key[s] : pv;
                unsigned long long mn = (key[s] > pv) ? pv : key[s];
                key[s] = takeMax ? mx : mn;
            }
        }
    }

    // ---- gather boxes into smem (sorted order) + area in regs ----
    float area[SLOTS];
    #pragma unroll
    for (int s = 0; s < SLOTS; ++s) {
        float4 Bt = make_float4(0.f, 0.f, 0.f, 0.f);
        if (key[s] != 0ull) {
            int idx = (int)(0xFFFFFFFFu - (unsigned)(key[s] & 0xFFFFFFFFull));
            Bt = __ldg(&bx[idx]);
        }
        sbox[s * 32 + lane] = Bt;
        area[s] = fmaxf(Bt.z - Bt.x, 0.0f) * fmaxf(Bt.w - Bt.y, 0.0f);
    }
    __syncwarp();

    // ---- greedy: zeros auto-kept; positives vs lane-local kept registers ----
    #pragma unroll 1
    for (int s = 0; s < SLOTS; ++s) {
        unsigned validm = __ballot_sync(0xFFFFFFFFu, key[s] != 0ull);
        if (!validm) break;                       // sorted: all later slots empty
        unsigned zerom = __ballot_sync(0xFFFFFFFFu, area[s] == 0.0f) & validm;
        unsigned posm  = validm & ~zerom;
        unsigned km = zerom;
        while (posm) {
            int l = __ffs(posm) - 1;
            posm &= posm - 1u;
            float4 Bt = sbox[s * 32 + l];         // broadcast LDS
            float  at = __shfl_sync(0xFFFFFFFFu, area[s], l);
            bool sup = false;
            #define KTEST(KB, KA, OFF) \
                if (OFF + lane < nkp) { \
                    float ix1 = fmaxf(KB.x, Bt.x), iy1 = fmaxf(KB.y, Bt.y); \
                    float ix2 = fminf(KB.z, Bt.z), iy2 = fminf(KB.w, Bt.w); \
                    float inter = fmaxf(ix2 - ix1, 0.0f) * fmaxf(iy2 - iy1, 0.0f); \
                    float iou = inter / (KA + at - inter + 1e-9f); \
                    sup |= (iou > IOU_T); }
            KTEST(kb0, ka0, 0) KTEST(kb1, ka1, 32) KTEST(kb2, ka2, 64) KTEST(kb3, ka3, 96)
            #undef KTEST
            if (!__any_sync(0xFFFFFFFFu, sup)) {
                km |= 1u << l;
                if (nkp < NMSMAX) {
                    if (lane == (nkp & 31)) {
                        int sl = nkp >> 5;
                        if      (sl == 0) { kb0 = Bt; ka0 = at; }
                        else if (sl == 1) { kb1 = Bt; ka1 = at; }
                        else if (sl == 2) { kb2 = Bt; ka2 = at; }
                        else              { kb3 = Bt; ka3 = at; }
                    }
                    ++nkp;
                }
            }
        }
        // scatter kept of this slot
        int myr = ns + __popc(km & ((1u << lane) - 1u));
        if (((km >> lane) & 1u) && myr < NMSMAX) {
            int o = bc * NMSMAX + myr;
            g_selscore[o] = funmap((unsigned)(key[s] >> 32));
            g_selbox[o]   = sbox[s * 32 + lane];
        }
        ns += __popc(km);
        if (ns >= NMSMAX) break;
    }
}

__global__ void __launch_bounds__(32 * WPB) nms_topk_kernel(const float* __restrict__ y,
                                                            float* __restrict__ out)
{
    extern __shared__ char dyn[];
    const int wid  = threadIdx.x >> 5;
    const int lane = threadIdx.x & 31;
    const int bc   = blockIdx.x * WPB + wid;
    const int b    = bc / NCLS;
    const int c    = bc - b * NCLS;
    const float4* bx = g_boxes + (size_t)b * NN;
    float4* sbox = ((float4*)dyn) + wid * 512;

    const unsigned LO = fmap(0.975f);
    int ns = 0, nkp = 0;
    float4 kb0 = {0,0,0,0}, kb1 = {0,0,0,0}, kb2 = {0,0,0,0}, kb3 = {0,0,0,0};
    float  ka0 = 0, ka1 = 0, ka2 = 0, ka3 = 0;

    int cnt0 = g_candcnt[bc];
    bool haveList = (cnt0 <= CAP);
    unsigned nextHi = haveList ? LO : 0xFFFFFFFFu;

    if (haveList && cnt0 > 0) {
        if (cnt0 <= 256) process_window<8> (g_cand + bc * CAP, cnt0, bx, bc, lane, sbox,
                                            ns, nkp, kb0, kb1, kb2, kb3, ka0, ka1, ka2, ka3);
        else             process_window<16>(g_cand + bc * CAP, cnt0, bx, bc, lane, sbox,
                                            ns, nkp, kb0, kb1, kb2, kb3, ka0, ka1, ka2, ka3);
    }

    // exact continuation: descend score windows over raw y (warp-scoped)
    while (ns < NMSMAX && nextHi > 0) {
        unsigned lo2 = 0, hi2 = nextHi;
        int cnt;
        for (;;) {
            cnt = 0;
            for (int i = lane; i < NN; i += 32) {
                float v = y[((size_t)b * NN + i) * DCOL + 1 + c];
                bool take = false; unsigned m = 0;
                if (v > CONF_T) { m = fmap(v); take = (m >= lo2 && m < hi2); }
                unsigned msk = __ballot_sync(0xFFFFFFFFu, take);
                if (take) {
                    int off = cnt + __popc(msk & ((1u << lane) - 1u));
                    if (off < CAP)
                        g_cand[bc * CAP + off] = ((unsigned long long)m << 32) |
                                                 (unsigned)(0xFFFFFFFFu - (unsigned)i);
                }
                cnt += __popc(msk);
            }
            if (cnt <= CAP || hi2 - lo2 <= 1) break;
            lo2 = lo2 + ((hi2 - lo2) >> 1);
        }
        if (cnt > CAP) cnt = CAP;
        __threadfence_block();
        __syncwarp();
        if (cnt > 0) {
            if (cnt <= 256) process_window<8> (g_cand + bc * CAP, cnt, bx, bc, lane, sbox,
                                               ns, nkp, kb0, kb1, kb2, kb3, ka0, ka1, ka2, ka3);
            else            process_window<16>(g_cand + bc * CAP, cnt, bx, bc, lane, sbox,
                                               ns, nkp, kb0, kb1, kb2, kb3, ka0, ka1, ka2, ka3);
        }
        nextHi = lo2;
    }

    for (int j = ns + lane; j < NMSMAX; j += 32)
        g_selscore[bc * NMSMAX + j] = -INFINITY;

    // ---- last-block-of-batch runs the batch top-k ----
    __shared__ int s_last;
    __threadfence();
    __syncthreads();
    const int bb = blockIdx.x / BLK_PER_BATCH;
    if (threadIdx.x == 0)
        s_last = (atomicAdd(&g_batch_done[bb], 1) == BLK_PER_BATCH - 1);
    __syncthreads();
    if (!s_last) return;
    __threadfence();

    const int tid = threadIdx.x;
    const int NK  = NCLS * NMSMAX;                               // 2000
    unsigned long long* keys = (unsigned long long*)dyn;         // 16000 B
    unsigned char*      cnt8 = (unsigned char*)(dyn + 16000);    // 40000 B

    for (int k = tid; k < NK; k += 128) {
        float s = __ldcg(&g_selscore[bb * NK + k]);
        keys[k] = ((unsigned long long)fmap(s) << 32) |
                  (unsigned)(0xFFFFFFFFu - (unsigned)k);
    }
    __syncthreads();

    // 400 class pairs (incl. self) * 4 segments of 25: two-pointer counts
    for (int u = tid; u < 400 * 4; u += 128) {
        int pair = u >> 2;
        int seg  = u & 3;
        int c0 = pair / NCLS;
        int cc = pair - c0 * NCLS;
        const unsigned long long* A  = keys + c0 * NMSMAX;
        const unsigned long long* Bk = keys + cc * NMSMAX;
        int i0 = seg * 25;
        unsigned long long a = A[i0];
        int lo = 0, hi = NMSMAX;
        while (lo < hi) {
            int mid = (lo + hi) >> 1;
            if (Bk[mid] > a) lo = mid + 1; else hi = mid;
        }
        int jb = lo;
        cnt8[(c0 * NMSMAX + i0) * NCLS + cc] = (unsigned char)jb;
        for (int i = i0 + 1; i < i0 + 25; ++i) {
            a = A[i];
            while (jb < NMSMAX && Bk[jb] > a) ++jb;
            cnt8[(c0 * NMSMAX + i) * NCLS + cc] = (unsigned char)jb;
        }
    }
    __syncthreads();

    for (int k = tid; k < NK; k += 128) {
        int rank = 0;
        const unsigned char* row = cnt8 + k * NCLS;
        #pragma unroll
        for (int cc = 0; cc < NCLS; ++cc) rank += row[cc];
        if (rank < TOPK) {
            unsigned long long key = keys[k];
            unsigned hi32 = (unsigned)(key >> 32);
            float* o = out + ((size_t)bb * TOPK + rank) * 6;
            if (hi32 != FM_NEGINF) {
                int c0 = k / NMSMAX;
                float4 box = __ldcg(&g_selbox[bb * NK + k]);
                o[0] = (float)c0 + 1.0f;
                o[1] = funmap(hi32);
                o[2] = box.x; o[3] = box.y; o[4] = box.z; o[5] = box.w;
            } else {
                o[0] = 1.0f; o[1] = 0.0f;
                o[2] = 0.0f; o[3] = 0.0f; o[4] = 0.0f; o[5] = 0.0f;
            }
        }
    }

    // reset per-batch state for next replay
    if (tid < NCLS) g_candcnt[bb * NCLS + tid] = 0;
    if (tid == 0)   g_batch_done[bb] = 0;
}

// -----------------------------------------------------------------------------
extern "C" void kernel_launch(void* const* d_in, const int* in_sizes, int n_in,
                              void* d_out, int out_size)
{
    const float* y = (const float*)d_in[0];
    float* out = (float*)d_out;
    cudaFuncSetAttribute(nms_topk_kernel, cudaFuncAttributeMaxDynamicSharedMemorySize, DYN_SMEM);
    decode_kernel<<<BB * NTILES, 256>>>(y);
    nms_topk_kernel<<<NMSBLOCKS, 32 * WPB, DYN_SMEM>>>(y, out);
}

// round 10
// speedup vs baseline: 2.4951x; 2.4951x over previous
#include <cuda_runtime.h>
#include <math.h>
#include <stdint.h>

#define BB     32
#define NN     8732
#define NCLS   20
#define DCOL   33
#define NMSMAX 100
#define TOPK   200
#define CONF_T 0.01f
#define IOU_T  0.45f
#define TILE   128
#define NTILES 69            // ceil(8732/128)
#define NBC    (BB * NCLS)   // 640
#define CAP    384
#define STAGE  64

// ---------------- scratch ----------------
__device__ float4             g_boxes   [(size_t)BB * NN];
__device__ int                g_candcnt [NBC];            // zero-init; topk resets
__device__ unsigned long long g_cand    [NBC * CAP];
__device__ float              g_selscore[NBC * NMSMAX];
__device__ float4             g_selbox  [NBC * NMSMAX];

// monotonic float <-> u32 order-preserving map
__device__ __forceinline__ unsigned fmap(float f) {
    unsigned u = __float_as_uint(f);
    return (u & 0x80000000u) ? ~u : (u | 0x80000000u);
}
__device__ __forceinline__ float funmap(unsigned u) {
    return __uint_as_float((u & 0x80000000u) ? (u & 0x7FFFFFFFu) : ~u);
}
#define FM_NEGINF 0x007FFFFFu   // fmap(-inf)

__device__ __forceinline__ float4 decode_box_row(const float* __restrict__ r)
{
    float cx_p = r[21], cy_p = r[22], w_p = r[23], h_p = r[24];
    float xa1  = r[25], ya1  = r[26], xa2 = r[27], ya2 = r[28];
    float vcx  = r[29], vcy  = r[30], vw  = r[31], vh  = r[32];
    float w_a = xa2 - xa1, h_a = ya2 - ya1;
    float cx_a = (xa2 + xa1) * 0.5f, cy_a = (ya2 + ya1) * 0.5f;
    float cx = cx_p * vcx * w_a + cx_a;
    float cy = cy_p * vcy * h_a + cy_a;
    float w  = expf(w_p * vw) * w_a;
    float h  = expf(h_p * vh) * h_a;
    float4 o;
    o.x = (cx - 0.5f * w) * 512.0f;
    o.y = (cy - 0.5f * h) * 512.0f;
    o.z = (cx + 0.5f * w) * 512.0f;
    o.w = (cy + 0.5f * h) * 512.0f;
    return o;
}

// ---------------- phase 1: decode + staged candidate filter ----------------
__global__ void __launch_bounds__(256) decode_kernel(const float* __restrict__ y)
{
    __shared__ __align__(16) float sh[TILE * DCOL];
    __shared__ unsigned long long s_skey[NCLS * STAGE];
    __shared__ int s_scnt[NCLS];
    __shared__ int s_sbase[NCLS];

    const int tid = threadIdx.x;
    int blk = blockIdx.x;
    int b   = blk / NTILES;
    int t   = blk % NTILES;
    int n0  = t * TILE;
    int count = min(TILE, NN - n0);

    {   // vectorized tile load (count*DCOL % 4 == 0, base 16B-aligned)
        const float4* src4 = (const float4*)(y + ((size_t)b * NN + n0) * DCOL);
        float4* sh4 = (float4*)sh;
        int n4 = (count * DCOL) >> 2;
        for (int i = tid; i < n4; i += 256) sh4[i] = src4[i];
    }
    if (tid < NCLS) s_scnt[tid] = 0;
    __syncthreads();

    const unsigned LO = fmap(0.975f);
    if (count == TILE) {
        for (int k = tid; k < NCLS * TILE; k += 256) {
            int c  = k >> 7;
            int nn = k & (TILE - 1);
            float s = sh[nn * DCOL + 1 + c];
            if (s > CONF_T) {
                unsigned m = fmap(s);
                if (m >= LO) {
                    unsigned long long key = ((unsigned long long)m << 32) |
                                             (unsigned)(0xFFFFFFFFu - (unsigned)(n0 + nn));
                    int p = atomicAdd(&s_scnt[c], 1);
                    if (p < STAGE) s_skey[c * STAGE + p] = key;
                    else {
                        int bc = b * NCLS + c;
                        int q = atomicAdd(&g_candcnt[bc], 1);
                        if (q < CAP) g_cand[bc * CAP + q] = key;
                    }
                }
            }
        }
    } else {
        for (int k = tid; k < NCLS * count; k += 256) {
            int c  = k / count;
            int nn = k - c * count;
            float s = sh[nn * DCOL + 1 + c];
            if (s > CONF_T) {
                unsigned m = fmap(s);
                if (m >= LO) {
                    unsigned long long key = ((unsigned long long)m << 32) |
                                             (unsigned)(0xFFFFFFFFu - (unsigned)(n0 + nn));
                    int p = atomicAdd(&s_scnt[c], 1);
                    if (p < STAGE) s_skey[c * STAGE + p] = key;
                    else {
                        int bc = b * NCLS + c;
                        int q = atomicAdd(&g_candcnt[bc], 1);
                        if (q < CAP) g_cand[bc * CAP + q] = key;
                    }
                }
            }
        }
    }
    __syncthreads();

    if (tid < NCLS) {
        int n = min(s_scnt[tid], STAGE);
        s_sbase[tid] = (n > 0) ? atomicAdd(&g_candcnt[b * NCLS + tid], n) : 0;
    }
    __syncthreads();
    for (int k = tid; k < NCLS * STAGE; k += 256) {
        int c = k >> 6;
        int j = k & (STAGE - 1);
        if (j < min(s_scnt[c], STAGE)) {
            int q = s_sbase[c] + j;
            if (q < CAP) g_cand[(b * NCLS + c) * CAP + q] = s_skey[c * STAGE + j];
        }
    }

    if (tid < count)
        g_boxes[(size_t)b * NN + n0 + tid] = decode_box_row(sh + tid * DCOL);
}

// ---------------- phase 2: warp-scoped NMS, ONE warp-block per (b,c) --------
struct WarpSmem {
    float4 allbox[512];     // boxes in sorted order
    float4 kbox[NMSMAX];    // kept positive-area boxes (persist across windows)
    float  karea[NMSMAX];
};

template<int SLOTS>
__device__ __forceinline__ void process_window_impl(
    const unsigned long long* __restrict__ src, int cnt, const float4* __restrict__ bx,
    int bc, WarpSmem& W, int lane, int& ns, int& nkp)
{
    constexpr int LOG2N = (SLOTS == 8) ? 8 : 9;

    unsigned long long key[SLOTS];
    #pragma unroll
    for (int s = 0; s < SLOTS; ++s) {
        int p = s * 32 + lane;
        key[s] = (p < cnt) ? src[p] : 0ull;
    }

    // ---- warp bitonic sort, descending (slot-major: p = s*32 + lane) ----
    #pragma unroll
    for (int ksl = 1; ksl <= LOG2N; ++ksl) {
        const int ks = 1 << ksl;
        #pragma unroll
        for (int j = ks >> 1; j >= 32; j >>= 1) {
            const int js = j >> 5;
            #pragma unroll
            for (int s = 0; s < SLOTS; ++s) {
                const int sp = s ^ js;
                if (sp > s) {
                    bool descSeg = (((s * 32) & ks) == 0);
                    unsigned long long a = key[s], b2 = key[sp];
                    bool sw = descSeg ? (a < b2) : (a > b2);
                    if (sw) { key[s] = b2; key[sp] = a; }
                }
            }
        }
        for (int j = (ks >> 1) < 32 ? (ks >> 1) : 16; j > 0; j >>= 1) {
            #pragma unroll
            for (int s = 0; s < SLOTS; ++s) {
                int p = s * 32 + lane;
                unsigned long long pv = __shfl_xor_sync(0xFFFFFFFFu, key[s], j);
                bool lower   = ((lane & j) == 0);
                bool descSeg = ((p & ks) == 0);
                bool takeMax = (lower == descSeg);
                unsigned long long mx = (key[s] > pv) ? key[s] : pv;
                unsigned long long mn = (key[s] > pv) ? pv : key[s];
                key[s] = takeMax ? mx : mn;
            }
        }
    }

    // ---- fetch boxes + areas in sorted order ----
    float area[SLOTS];
    #pragma unroll
    for (int s = 0; s < SLOTS; ++s) {
        int p = s * 32 + lane;
        float4 Bt = make_float4(0.f, 0.f, 0.f, 0.f);
        if (key[s] != 0ull) {
            int idx = (int)(0xFFFFFFFFu - (unsigned)(key[s] & 0xFFFFFFFFull));
            Bt = __ldg(&bx[idx]);
        }
        W.allbox[p] = Bt;
        area[s] = fmaxf(Bt.z - Bt.x, 0.0f) * fmaxf(Bt.w - Bt.y, 0.0f);
    }
    __syncwarp();

    // ---- greedy: zeros auto-kept; positives tested vs kept-positive list ----
    #pragma unroll 1
    for (int s = 0; s < SLOTS; ++s) {
        if (ns >= NMSMAX) break;                       // exact: later ranks >= 100
        unsigned validm = __ballot_sync(0xFFFFFFFFu, key[s] != 0ull);
        if (!validm) break;                            // sorted: rest empty
        unsigned zerom  = __ballot_sync(0xFFFFFFFFu, area[s] == 0.0f) & validm;
        unsigned posm   = validm & ~zerom;
        unsigned km = zerom;
        while (posm) {
            int l = __ffs(posm) - 1;
            posm &= posm - 1u;
            float4 Bt = W.allbox[s * 32 + l];          // broadcast LDS
            float  at = __shfl_sync(0xFFFFFFFFu, area[s], l);
            bool sup = false;
            for (int j2 = lane; j2 < nkp; j2 += 32) {
                float4 Kj = W.kbox[j2];
                float ix1 = fmaxf(Kj.x, Bt.x), iy1 = fmaxf(Kj.y, Bt.y);
                float ix2 = fminf(Kj.z, Bt.z), iy2 = fminf(Kj.w, Bt.w);
                float inter = fmaxf(ix2 - ix1, 0.0f) * fmaxf(iy2 - iy1, 0.0f);
                float iou = inter / (W.karea[j2] + at - inter + 1e-9f);
                sup |= (iou > IOU_T);
            }
            if (!__any_sync(0xFFFFFFFFu, sup)) {
                km |= 1u << l;
                if (nkp < NMSMAX) {   // beyond 100 kept-positives cannot affect top-100
                    if (lane == 0) { W.kbox[nkp] = Bt; W.karea[nkp] = at; }
                    nkp++;
                    __syncwarp();
                }
            }
        }
        // scatter kept of this slot
        int myr = ns + __popc(km & ((1u << lane) - 1u));
        if (((km >> lane) & 1u) && myr < NMSMAX) {
            int o = bc * NMSMAX + myr;
            g_selscore[o] = funmap((unsigned)(key[s] >> 32));
            g_selbox[o]   = W.allbox[s * 32 + lane];
        }
        ns += __popc(km);
    }
}

// hot path: <=256 candidates (inlined, lean)
__device__ __forceinline__ void process_window8(
    const unsigned long long* src, int cnt, const float4* bx,
    int bc, WarpSmem& W, int lane, int& ns, int& nkp)
{
    process_window_impl<8>(src, cnt, bx, bc, W, lane, ns, nkp);
}
// rare path: 257..512 candidates (outlined to protect hot-path registers)
__device__ __noinline__ void process_window16(
    const unsigned long long* src, int cnt, const float4* bx,
    int bc, WarpSmem& W, int lane, int& ns, int& nkp)
{
    process_window_impl<16>(src, cnt, bx, bc, W, lane, ns, nkp);
}

__global__ void __launch_bounds__(32) nms_kernel(const float* __restrict__ y)
{
    __shared__ WarpSmem W;
    const int lane = threadIdx.x;
    const int bc   = blockIdx.x;
    const int b    = bc / NCLS;
    const int c    = bc - b * NCLS;
    const float4* bx = g_boxes + (size_t)b * NN;

    const unsigned LO = fmap(0.975f);
    int ns = 0, nkp = 0;

    int cnt0 = g_candcnt[bc];
    bool haveList = (cnt0 <= CAP);
    unsigned nextHi = haveList ? LO : 0xFFFFFFFFu;

    if (haveList && cnt0 > 0) {
        if (cnt0 <= 256) process_window8 (g_cand + bc * CAP, cnt0, bx, bc, W, lane, ns, nkp);
        else             process_window16(g_cand + bc * CAP, cnt0, bx, bc, W, lane, ns, nkp);
    }

    // exact continuation: descend score windows over raw y (warp-scoped, rare)
    while (ns < NMSMAX && nextHi > 0) {
        unsigned lo2 = 0, hi2 = nextHi;
        int cnt;
        for (;;) {
            cnt = 0;
            for (int i = lane; i < NN; i += 32) {
                float v = y[((size_t)b * NN + i) * DCOL + 1 + c];
                bool take = false; unsigned m = 0;
                if (v > CONF_T) { m = fmap(v); take = (m >= lo2 && m < hi2); }
                unsigned msk = __ballot_sync(0xFFFFFFFFu, take);
                if (take) {
                    int off = cnt + __popc(msk & ((1u << lane) - 1u));
                    if (off < CAP)
                        g_cand[bc * CAP + off] = ((unsigned long long)m << 32) |
                                                 (unsigned)(0xFFFFFFFFu - (unsigned)i);
                }
                cnt += __popc(msk);
            }
            if (cnt <= CAP || hi2 - lo2 <= 1) break;
            lo2 = lo2 + ((hi2 - lo2) >> 1);
        }
        if (cnt > CAP) cnt = CAP;
        __threadfence_block();
        __syncwarp();
        if (cnt > 0) {
            if (cnt <= 256) process_window8 (g_cand + bc * CAP, cnt, bx, bc, W, lane, ns, nkp);
            else            process_window16(g_cand + bc * CAP, cnt, bx, bc, W, lane, ns, nkp);
        }
        nextHi = lo2;
    }

    for (int j = ns + lane; j < NMSMAX; j += 32)
        g_selscore[bc * NMSMAX + j] = -INFINITY;
}

// ---------------- phase 3: rank-scatter top-200, one CTA per (b,c0) --------
__global__ void __launch_bounds__(128) topk_kernel(float* __restrict__ out)
{
    const int bc  = blockIdx.x;
    const int b   = bc / NCLS;
    const int c0  = bc - b * NCLS;
    const int tid = threadIdx.x;
    const int NK  = NCLS * NMSMAX;

    __shared__ unsigned long long keys[NCLS * NMSMAX];
    __shared__ int s_rank[NMSMAX];

    for (int k = tid; k < NK; k += 128) {
        float s = g_selscore[b * NK + k];
        keys[k] = ((unsigned long long)fmap(s) << 32) |
                  (unsigned)(0xFFFFFFFFu - (unsigned)k);
    }
    if (tid < NMSMAX) s_rank[tid] = tid;
    __syncthreads();

    for (int u = tid; u < NMSMAX * (NCLS - 1); u += 128) {
        int i = u / (NCLS - 1);
        int j = u - i * (NCLS - 1);
        int cc = j + (j >= c0);
        unsigned long long my = keys[c0 * NMSMAX + i];
        const unsigned long long* L = keys + cc * NMSMAX;
        int lo = 0, hi = NMSMAX;
        while (lo < hi) {
            int mid = (lo + hi) >> 1;
            if (L[mid] > my) lo = mid + 1; else hi = mid;
        }
        atomicAdd(&s_rank[i], lo);
    }
    __syncthreads();

    if (tid < NMSMAX) {
        int r = s_rank[tid];
        if (r < TOPK) {
            unsigned long long key = keys[c0 * NMSMAX + tid];
            unsigned hi32 = (unsigned)(key >> 32);
            float* o = out + ((size_t)b * TOPK + r) * 6;
            if (hi32 != FM_NEGINF) {
                float4 box = g_selbox[bc * NMSMAX + tid];
                o[0] = (float)c0 + 1.0f;
                o[1] = funmap(hi32);
                o[2] = box.x; o[3] = box.y; o[4] = box.z; o[5] = box.w;
            } else {
                o[0] = 1.0f; o[1] = 0.0f;
                o[2] = 0.0f; o[3] = 0.0f; o[4] = 0.0f; o[5] = 0.0f;
            }
        }
    }
    if (tid == 0) g_candcnt[bc] = 0;   // reset for next replay
}

// -----------------------------------------------------------------------------
extern "C" void kernel_launch(void* const* d_in, const int* in_sizes, int n_in,
                              void* d_out, int out_size)
{
    const float* y = (const float*)d_in[0];
    float* out = (float*)d_out;
    decode_kernel<<<BB * NTILES, 256>>>(y);
    nms_kernel<<<NBC, 32>>>(y);
    topk_kernel<<<NBC, 128>>>(out);
}

// round 11
// speedup vs baseline: 2.7578x; 1.1053x over previous
#include <cuda_runtime.h>
#include <math.h>
#include <stdint.h>

#define BB     32
#define NN     8732
#define NCLS   20
#define DCOL   33
#define NMSMAX 100
#define TOPK   200
#define CONF_T 0.01f
#define IOU_T  0.45f
#define TILE   128
#define NTILES 69            // ceil(8732/128)
#define NBC    (BB * NCLS)   // 640
#define CAP    384
#define STAGE  64
#define TK_T   256

// ---------------- scratch ----------------
__device__ float4             g_boxes   [(size_t)BB * NN];
__device__ int                g_candcnt [NBC];            // reset by init_kernel
__device__ unsigned long long g_cand    [NBC * CAP];
__device__ float              g_selscore[NBC * NMSMAX];
__device__ float4             g_selbox  [NBC * NMSMAX];

// monotonic float <-> u32 order-preserving map
__device__ __forceinline__ unsigned fmap(float f) {
    unsigned u = __float_as_uint(f);
    return (u & 0x80000000u) ? ~u : (u | 0x80000000u);
}
__device__ __forceinline__ float funmap(unsigned u) {
    return __uint_as_float((u & 0x80000000u) ? (u & 0x7FFFFFFFu) : ~u);
}
#define FM_NEGINF 0x007FFFFFu   // fmap(-inf)

__device__ __forceinline__ float4 decode_box_row(const float* __restrict__ r)
{
    float cx_p = r[21], cy_p = r[22], w_p = r[23], h_p = r[24];
    float xa1  = r[25], ya1  = r[26], xa2 = r[27], ya2 = r[28];
    float vcx  = r[29], vcy  = r[30], vw  = r[31], vh  = r[32];
    float w_a = xa2 - xa1, h_a = ya2 - ya1;
    float cx_a = (xa2 + xa1) * 0.5f, cy_a = (ya2 + ya1) * 0.5f;
    float cx = cx_p * vcx * w_a + cx_a;
    float cy = cy_p * vcy * h_a + cy_a;
    float w  = expf(w_p * vw) * w_a;
    float h  = expf(h_p * vh) * h_a;
    float4 o;
    o.x = (cx - 0.5f * w) * 512.0f;
    o.y = (cy - 0.5f * h) * 512.0f;
    o.z = (cx + 0.5f * w) * 512.0f;
    o.w = (cy + 0.5f * h) * 512.0f;
    return o;
}

// ---------------- phase 0: reset counters ----------------
__global__ void init_kernel() { g_candcnt[threadIdx.x] = 0; }

// ---------------- phase 1: decode + staged candidate filter ----------------
__global__ void __launch_bounds__(256) decode_kernel(const float* __restrict__ y)
{
    __shared__ __align__(16) float sh[TILE * DCOL];
    __shared__ unsigned long long s_skey[NCLS * STAGE];
    __shared__ int s_scnt[NCLS];
    __shared__ int s_sbase[NCLS];

    const int tid = threadIdx.x;
    int blk = blockIdx.x;
    int b   = blk / NTILES;
    int t   = blk % NTILES;
    int n0  = t * TILE;
    int count = min(TILE, NN - n0);

    {   // vectorized tile load (count*DCOL % 4 == 0, base 16B-aligned)
        const float4* src4 = (const float4*)(y + ((size_t)b * NN + n0) * DCOL);
        float4* sh4 = (float4*)sh;
        int n4 = (count * DCOL) >> 2;
        for (int i = tid; i < n4; i += 256) sh4[i] = src4[i];
    }
    if (tid < NCLS) s_scnt[tid] = 0;
    __syncthreads();

    const unsigned LO = fmap(0.975f);
    if (count == TILE) {
        for (int k = tid; k < NCLS * TILE; k += 256) {
            int c  = k >> 7;
            int nn = k & (TILE - 1);
            float s = sh[nn * DCOL + 1 + c];
            if (s > CONF_T) {
                unsigned m = fmap(s);
                if (m >= LO) {
                    unsigned long long key = ((unsigned long long)m << 32) |
                                             (unsigned)(0xFFFFFFFFu - (unsigned)(n0 + nn));
                    int p = atomicAdd(&s_scnt[c], 1);
                    if (p < STAGE) s_skey[c * STAGE + p] = key;
                    else {
                        int bc = b * NCLS + c;
                        int q = atomicAdd(&g_candcnt[bc], 1);
                        if (q < CAP) g_cand[bc * CAP + q] = key;
                    }
                }
            }
        }
    } else {
        for (int k = tid; k < NCLS * count; k += 256) {
            int c  = k / count;
            int nn = k - c * count;
            float s = sh[nn * DCOL + 1 + c];
            if (s > CONF_T) {
                unsigned m = fmap(s);
                if (m >= LO) {
                    unsigned long long key = ((unsigned long long)m << 32) |
                                             (unsigned)(0xFFFFFFFFu - (unsigned)(n0 + nn));
                    int p = atomicAdd(&s_scnt[c], 1);
                    if (p < STAGE) s_skey[c * STAGE + p] = key;
                    else {
                        int bc = b * NCLS + c;
                        int q = atomicAdd(&g_candcnt[bc], 1);
                        if (q < CAP) g_cand[bc * CAP + q] = key;
                    }
                }
            }
        }
    }
    __syncthreads();

    if (tid < NCLS) {
        int n = min(s_scnt[tid], STAGE);
        s_sbase[tid] = (n > 0) ? atomicAdd(&g_candcnt[b * NCLS + tid], n) : 0;
    }
    __syncthreads();
    for (int k = tid; k < NCLS * STAGE; k += 256) {
        int c = k >> 6;
        int j = k & (STAGE - 1);
        if (j < min(s_scnt[c], STAGE)) {
            int q = s_sbase[c] + j;
            if (q < CAP) g_cand[(b * NCLS + c) * CAP + q] = s_skey[c * STAGE + j];
        }
    }

    if (tid < count)
        g_boxes[(size_t)b * NN + n0 + tid] = decode_box_row(sh + tid * DCOL);
}

// ---------------- phase 2: warp-scoped NMS, ONE warp-block per (b,c) --------
struct WarpSmem {
    float4 allbox[512];     // boxes in sorted order
    float4 kbox[NMSMAX];    // kept positive-area boxes (persist across windows)
    float  karea[NMSMAX];
};

template<int SLOTS>
__device__ __forceinline__ void process_window_impl(
    const unsigned long long* __restrict__ src, int cnt, const float4* __restrict__ bx,
    int bc, WarpSmem& W, int lane, int& ns, int& nkp)
{
    constexpr int LOG2N = (SLOTS == 8) ? 8 : 9;

    unsigned long long key[SLOTS];
    #pragma unroll
    for (int s = 0; s < SLOTS; ++s) {
        int p = s * 32 + lane;
        key[s] = (p < cnt) ? src[p] : 0ull;
    }

    // ---- warp bitonic sort, descending (slot-major: p = s*32 + lane) ----
    #pragma unroll
    for (int ksl = 1; ksl <= LOG2N; ++ksl) {
        const int ks = 1 << ksl;
        #pragma unroll
        for (int j = ks >> 1; j >= 32; j >>= 1) {
            const int js = j >> 5;
            #pragma unroll
            for (int s = 0; s < SLOTS; ++s) {
                const int sp = s ^ js;
                if (sp > s) {
                    bool descSeg = (((s * 32) & ks) == 0);
                    unsigned long long a = key[s], b2 = key[sp];
                    bool sw = descSeg ? (a < b2) : (a > b2);
                    if (sw) { key[s] = b2; key[sp] = a; }
                }
            }
        }
        for (int j = (ks >> 1) < 32 ? (ks >> 1) : 16; j > 0; j >>= 1) {
            #pragma unroll
            for (int s = 0; s < SLOTS; ++s) {
                int p = s * 32 + lane;
                unsigned long long pv = __shfl_xor_sync(0xFFFFFFFFu, key[s], j);
                bool lower   = ((lane & j) == 0);
                bool descSeg = ((p & ks) == 0);
                bool takeMax = (lower == descSeg);
                unsigned long long mx = (key[s] > pv) ? key[s] : pv;
                unsigned long long mn = (key[s] > pv) ? pv : key[s];
                key[s] = takeMax ? mx : mn;
            }
        }
    }

    // ---- fetch boxes + areas in sorted order ----
    float area[SLOTS];
    #pragma unroll
    for (int s = 0; s < SLOTS; ++s) {
        int p = s * 32 + lane;
        float4 Bt = make_float4(0.f, 0.f, 0.f, 0.f);
        if (key[s] != 0ull) {
            int idx = (int)(0xFFFFFFFFu - (unsigned)(key[s] & 0xFFFFFFFFull));
            Bt = __ldg(&bx[idx]);
        }
        W.allbox[p] = Bt;
        area[s] = fmaxf(Bt.z - Bt.x, 0.0f) * fmaxf(Bt.w - Bt.y, 0.0f);
    }
    __syncwarp();

    // ---- greedy: zeros auto-kept; positives tested vs kept-positive list ----
    #pragma unroll 1
    for (int s = 0; s < SLOTS; ++s) {
        if (ns >= NMSMAX) break;                       // exact: later ranks >= 100
        unsigned validm = __ballot_sync(0xFFFFFFFFu, key[s] != 0ull);
        if (!validm) break;                            // sorted: rest empty
        unsigned zerom  = __ballot_sync(0xFFFFFFFFu, area[s] == 0.0f) & validm;
        unsigned posm   = validm & ~zerom;
        unsigned km = zerom;
        while (posm) {
            int l = __ffs(posm) - 1;
            posm &= posm - 1u;
            float4 Bt = W.allbox[s * 32 + l];          // broadcast LDS
            float  at = __shfl_sync(0xFFFFFFFFu, area[s], l);
            bool sup = false;
            for (int j2 = lane; j2 < nkp; j2 += 32) {
                float4 Kj = W.kbox[j2];
                float ix1 = fmaxf(Kj.x, Bt.x), iy1 = fmaxf(Kj.y, Bt.y);
                float ix2 = fminf(Kj.z, Bt.z), iy2 = fminf(Kj.w, Bt.w);
                float inter = fmaxf(ix2 - ix1, 0.0f) * fmaxf(iy2 - iy1, 0.0f);
                float iou = inter / (W.karea[j2] + at - inter + 1e-9f);
                sup |= (iou > IOU_T);
            }
            if (!__any_sync(0xFFFFFFFFu, sup)) {
                km |= 1u << l;
                if (nkp < NMSMAX) {   // beyond 100 kept-positives cannot affect top-100
                    if (lane == 0) { W.kbox[nkp] = Bt; W.karea[nkp] = at; }
                    nkp++;
                    __syncwarp();
                }
            }
        }
        // scatter kept of this slot
        int myr = ns + __popc(km & ((1u << lane) - 1u));
        if (((km >> lane) & 1u) && myr < NMSMAX) {
            int o = bc * NMSMAX + myr;
            g_selscore[o] = funmap((unsigned)(key[s] >> 32));
            g_selbox[o]   = W.allbox[s * 32 + lane];
        }
        ns += __popc(km);
    }
}

// hot path: <=256 candidates (inlined, lean)
__device__ __forceinline__ void process_window8(
    const unsigned long long* src, int cnt, const float4* bx,
    int bc, WarpSmem& W, int lane, int& ns, int& nkp)
{
    process_window_impl<8>(src, cnt, bx, bc, W, lane, ns, nkp);
}
// rare path: 257..512 candidates (outlined to protect hot-path registers)
__device__ __noinline__ void process_window16(
    const unsigned long long* src, int cnt, const float4* bx,
    int bc, WarpSmem& W, int lane, int& ns, int& nkp)
{
    process_window_impl<16>(src, cnt, bx, bc, W, lane, ns, nkp);
}

__global__ void __launch_bounds__(32) nms_kernel(const float* __restrict__ y)
{
    __shared__ WarpSmem W;
    const int lane = threadIdx.x;
    const int bc   = blockIdx.x;
    const int b    = bc / NCLS;
    const int c    = bc - b * NCLS;
    const float4* bx = g_boxes + (size_t)b * NN;

    const unsigned LO = fmap(0.975f);
    int ns = 0, nkp = 0;

    int cnt0 = g_candcnt[bc];
    bool haveList = (cnt0 <= CAP);
    unsigned nextHi = haveList ? LO : 0xFFFFFFFFu;

    if (haveList && cnt0 > 0) {
        if (cnt0 <= 256) process_window8 (g_cand + bc * CAP, cnt0, bx, bc, W, lane, ns, nkp);
        else             process_window16(g_cand + bc * CAP, cnt0, bx, bc, W, lane, ns, nkp);
    }

    // exact continuation: descend score windows over raw y (warp-scoped, rare)
    while (ns < NMSMAX && nextHi > 0) {
        unsigned lo2 = 0, hi2 = nextHi;
        int cnt;
        for (;;) {
            cnt = 0;
            for (int i = lane; i < NN; i += 32) {
                float v = y[((size_t)b * NN + i) * DCOL + 1 + c];
                bool take = false; unsigned m = 0;
                if (v > CONF_T) { m = fmap(v); take = (m >= lo2 && m < hi2); }
                unsigned msk = __ballot_sync(0xFFFFFFFFu, take);
                if (take) {
                    int off = cnt + __popc(msk & ((1u << lane) - 1u));
                    if (off < CAP)
                        g_cand[bc * CAP + off] = ((unsigned long long)m << 32) |
                                                 (unsigned)(0xFFFFFFFFu - (unsigned)i);
                }
                cnt += __popc(msk);
            }
            if (cnt <= CAP || hi2 - lo2 <= 1) break;
            lo2 = lo2 + ((hi2 - lo2) >> 1);
        }
        if (cnt > CAP) cnt = CAP;
        __threadfence_block();
        __syncwarp();
        if (cnt > 0) {
            if (cnt <= 256) process_window8 (g_cand + bc * CAP, cnt, bx, bc, W, lane, ns, nkp);
            else            process_window16(g_cand + bc * CAP, cnt, bx, bc, W, lane, ns, nkp);
        }
        nextHi = lo2;
    }

    for (int j = ns + lane; j < NMSMAX; j += 32)
        g_selscore[bc * NMSMAX + j] = -INFINITY;
}

// ---------------- phase 3: rank-scatter top-200, one CTA per (b,c0) --------
// Mapping u = j*NMSMAX + i: each warp searches ONE other-class list with 32
// consecutive (sorted) queries -> broadcast-friendly LDS, and the rank
// atomics hit 32 distinct addresses (conflict-free).
__global__ void __launch_bounds__(TK_T) topk_kernel(float* __restrict__ out)
{
    const int bc  = blockIdx.x;
    const int b   = bc / NCLS;
    const int c0  = bc - b * NCLS;
    const int tid = threadIdx.x;
    const int NK  = NCLS * NMSMAX;

    __shared__ unsigned long long keys[NCLS * NMSMAX];
    __shared__ int s_rank[NMSMAX];

    for (int k = tid; k < NK; k += TK_T) {
        float s = g_selscore[b * NK + k];
        keys[k] = ((unsigned long long)fmap(s) << 32) |
                  (unsigned)(0xFFFFFFFFu - (unsigned)k);
    }
    if (tid < NMSMAX) s_rank[tid] = tid;
    __syncthreads();

    for (int u = tid; u < (NCLS - 1) * NMSMAX; u += TK_T) {
        int j = u / NMSMAX;            // other-class slot 0..18
        int i = u - j * NMSMAX;        // own-list position 0..99
        int cc = j + (j >= c0);
        unsigned long long my = keys[c0 * NMSMAX + i];
        const unsigned long long* L = keys + cc * NMSMAX;
        int lo = 0, hi = NMSMAX;
        while (lo < hi) {
            int mid = (lo + hi) >> 1;
            if (L[mid] > my) lo = mid + 1; else hi = mid;
        }
        atomicAdd(&s_rank[i], lo);
    }
    __syncthreads();

    if (tid < NMSMAX) {
        int r = s_rank[tid];
        if (r < TOPK) {
            unsigned long long key = keys[c0 * NMSMAX + tid];
            unsigned hi32 = (unsigned)(key >> 32);
            float* o = out + ((size_t)b * TOPK + r) * 6;
            if (hi32 != FM_NEGINF) {
                float4 box = g_selbox[bc * NMSMAX + tid];
                o[0] = (float)c0 + 1.0f;
                o[1] = funmap(hi32);
                o[2] = box.x; o[3] = box.y; o[4] = box.z; o[5] = box.w;
            } else {
                o[0] = 1.0f; o[1] = 0.0f;
                o[2] = 0.0f; o[3] = 0.0f; o[4] = 0.0f; o[5] = 0.0f;
            }
        }
    }
}

// -----------------------------------------------------------------------------
extern "C" void kernel_launch(void* const* d_in, const int* in_sizes, int n_in,
                              void* d_out, int out_size)
{
    const float* y = (const float*)d_in[0];
    float* out = (float*)d_out;
    // 4-kernel graph: the profiled 4th launch is topk_kernel (prime suspect).
    init_kernel<<<1, NBC>>>();
    decode_kernel<<<BB * NTILES, 256>>>(y);
    nms_kernel<<<NBC, 32>>>(y);
    topk_kernel<<<NBC, TK_T>>>(out);
}